// round 17
// baseline (speedup 1.0000x reference)
#include <cuda_runtime.h>
#include <cuda_bf16.h>
#include <cstdint>

static const int NN = 50000;
static const int NE = 600000;
static const int NRB = 3128;                 // ceil(50048/16) 16-row blocks
static const int NFRAG = NRB * 256;          // uint4 A-fragment groups (layer-0 only)

// ---------------- scratch ----------------
__device__ float g_h0[NN * 128];
__device__ float g_h1[NN * 128];
__device__ float g_y[NN * 128];              // y buffer A
__device__ float g_y2[NN * 128];             // y buffer B
__device__ uint4 g_afh[NFRAG];               // A fragments hi (layer 0)
__device__ uint4 g_afl[NFRAG];               // A fragments lo (layer 0)
__device__ uint4 g_wfh[10240];               // B fragments hi (all 6 matrices)
__device__ uint4 g_wfl[10240];               // B fragments lo
__device__ float g_invdeg[NN];
__device__ int   g_count[NN];
__device__ int   g_offs[NN + 1];
__device__ int   g_cursor[NN];
__device__ int   g_srcs[NE];
__device__ int   g_is64;
__device__ int   g_bsum[128];
__device__ int   g_bbase[128];

// B-fragment offsets (uint4 units)
static const int WF_S0 = 0;
static const int WF_N0 = 2048;
static const int WF_S1 = 4096;
static const int WF_N1 = 6144;
static const int WF_S2 = 8192;
static const int WF_N2 = 9216;

// fused-kernel smem layout (bytes)
static const int SH32_OFF = 0;               // float[128][132] = 67584
static const int AFH_OFF  = 67584;           // 2048 uint4 = 32768
static const int AFL_OFF  = 100352;          // 32768
static const int FUSED_SMEM = 133120;

__device__ __forceinline__ int edge_at(const void* ei, int i) {
    if (g_is64) return (int)((const long long*)ei)[i];
    return ((const int*)ei)[i];
}
__device__ __forceinline__ void mma_bf16(float* c, const uint32_t* a, const uint32_t* b) {
    asm volatile(
        "mma.sync.aligned.m16n8k16.row.col.f32.bf16.bf16.f32 "
        "{%0,%1,%2,%3}, {%4,%5,%6,%7}, {%8,%9}, {%0,%1,%2,%3};"
        : "+f"(c[0]), "+f"(c[1]), "+f"(c[2]), "+f"(c[3])
        : "r"(a[0]), "r"(a[1]), "r"(a[2]), "r"(a[3]), "r"(b[0]), "r"(b[1]));
}
__device__ __forceinline__ void split_bf16(float v, __nv_bfloat16& h, __nv_bfloat16& l) {
    h = __float2bfloat16(v);
    l = __float2bfloat16(v - __bfloat162float(h));
}
__device__ __forceinline__ void pack2(float a, float b, uint32_t& hw, uint32_t& lw) {
    __nv_bfloat16 ha, la, hb, lb;
    split_bf16(a, ha, la);
    split_bf16(b, hb, lb);
    __nv_bfloat162 ph; ph.x = ha; ph.y = hb;
    __nv_bfloat162 pl; pl.x = la; pl.y = lb;
    hw = *(uint32_t*)&ph;
    lw = *(uint32_t*)&pl;
}

// ---------------- dtype probe ----------------
__global__ void init_flag_kernel() { g_is64 = 1; }
__global__ void detect_kernel(const void* ei) {
    int i = blockIdx.x * blockDim.x + threadIdx.x;
    int bad = 0;
    if (i < 2 * NE) {
        long long v = ((const long long*)ei)[i];
        bad = (v < 0 || v >= NN) ? 1 : 0;
    }
    if (__syncthreads_or(bad)) {
        if (threadIdx.x == 0) g_is64 = 0;
    }
}

// ---------------- combined conv: x -> A frags, W* -> B frags ----------------
__global__ void conv_all_kernel(const float* __restrict__ x,
                                const float* __restrict__ W0s, const float* __restrict__ W0n,
                                const float* __restrict__ W1s, const float* __restrict__ W1n,
                                const float* __restrict__ W2s, const float* __restrict__ W2n)
{
    if (blockIdx.x < NRB) {
        const float2* src = (const float2*)x;
        int i = blockIdx.x * 256 + threadIdx.x;
        int rb = i >> 8, ks = (i >> 5) & 7, lane = i & 31;
        int r0 = rb * 16 + (lane >> 2), r1 = r0 + 8;
        int cp0 = ks * 8 + (lane & 3), cp1 = cp0 + 4;
        const float2 z = make_float2(0.f, 0.f);
        float2 v00 = (r0 < NN) ? src[(size_t)r0 * 64 + cp0] : z;
        float2 v10 = (r1 < NN) ? src[(size_t)r1 * 64 + cp0] : z;
        float2 v01 = (r0 < NN) ? src[(size_t)r0 * 64 + cp1] : z;
        float2 v11 = (r1 < NN) ? src[(size_t)r1 * 64 + cp1] : z;
        uint4 h, l;
        pack2(v00.x, v00.y, h.x, l.x);
        pack2(v10.x, v10.y, h.y, l.y);
        pack2(v01.x, v01.y, h.z, l.z);
        pack2(v11.x, v11.y, h.w, l.w);
        g_afh[i] = h;
        g_afl[i] = l;
    } else {
        int i = (blockIdx.x - NRB) * 256 + threadIdx.x;
        if (i >= 10240) return;
        const float* src;
        int off, N;
        if      (i < 2048) { src = W0s; off = WF_S0; N = 128; }
        else if (i < 4096) { src = W0n; off = WF_N0; N = 128; }
        else if (i < 6144) { src = W1s; off = WF_S1; N = 128; }
        else if (i < 8192) { src = W1n; off = WF_N1; N = 128; }
        else if (i < 9216) { src = W2s; off = WF_S2; N = 64;  }
        else               { src = W2n; off = WF_N2; N = 64;  }
        int j = i - off;
        int lane = j & 31, ks = (j >> 5) & 7, n16 = j >> 8;
        int nE = n16 * 16 + (lane >> 2), nO = nE + 8;
        int k0 = ks * 16 + (lane & 3) * 2;
        uint4 h, l;
        pack2(src[(size_t)k0 * N + nE],       src[(size_t)(k0 + 1) * N + nE], h.x, l.x);
        pack2(src[(size_t)(k0 + 8) * N + nE], src[(size_t)(k0 + 9) * N + nE], h.y, l.y);
        pack2(src[(size_t)k0 * N + nO],       src[(size_t)(k0 + 1) * N + nO], h.z, l.z);
        pack2(src[(size_t)(k0 + 8) * N + nO], src[(size_t)(k0 + 9) * N + nO], h.w, l.w);
        g_wfh[i] = h;
        g_wfl[i] = l;
    }
}

// ---------------- CSR build ----------------
__global__ void zero_count_kernel() {
    int i = blockIdx.x * blockDim.x + threadIdx.x;
    if (i < NN) g_count[i] = 0;
}
__global__ void hist_kernel(const void* ei) {
    int i = blockIdx.x * blockDim.x + threadIdx.x;
    if (i < NE) {
        int d = edge_at(ei, NE + i);
        d = min(max(d, 0), NN - 1);
        atomicAdd(&g_count[d], 1);
    }
}

static const int SCAN_SEG = 512;
static const int SCAN_THR = 256;
static const int SCAN_NB  = (NN + SCAN_SEG - 1) / SCAN_SEG;  // 98

__global__ void scan1_kernel() {
    __shared__ int red[SCAN_THR];
    int b = blockIdx.x, t = threadIdx.x;
    int i0 = b * SCAN_SEG + 2 * t, i1 = i0 + 1;
    int s = 0;
    if (i0 < NN) s += g_count[i0];
    if (i1 < NN) s += g_count[i1];
    red[t] = s;
    __syncthreads();
    for (int d = SCAN_THR / 2; d > 0; d >>= 1) {
        if (t < d) red[t] += red[t + d];
        __syncthreads();
    }
    if (t == 0) g_bsum[b] = red[0];
}
__global__ void scan2_kernel() {
    __shared__ int sh[128];
    int t = threadIdx.x;
    sh[t] = (t < SCAN_NB) ? g_bsum[t] : 0;
    __syncthreads();
    for (int d = 1; d < 128; d <<= 1) {
        int v = sh[t];
        int u = (t >= d) ? sh[t - d] : 0;
        __syncthreads();
        sh[t] = v + u;
        __syncthreads();
    }
    if (t < SCAN_NB) g_bbase[t] = sh[t] - g_bsum[t];
    if (t == 127) g_offs[NN] = sh[127];
}
__global__ void scan3_kernel() {
    __shared__ int sh[SCAN_THR];
    int b = blockIdx.x, t = threadIdx.x;
    int i0 = b * SCAN_SEG + 2 * t, i1 = i0 + 1;
    int c0 = (i0 < NN) ? g_count[i0] : 0;
    int c1 = (i1 < NN) ? g_count[i1] : 0;
    int s = c0 + c1;
    sh[t] = s;
    __syncthreads();
    for (int d = 1; d < SCAN_THR; d <<= 1) {
        int v = sh[t];
        int u = (t >= d) ? sh[t - d] : 0;
        __syncthreads();
        sh[t] = v + u;
        __syncthreads();
    }
    int tb = g_bbase[b] + sh[t] - s;
    if (i0 < NN) { g_offs[i0] = tb;      g_cursor[i0] = tb;      g_invdeg[i0] = 1.0f / fmaxf((float)c0, 1.0f); }
    if (i1 < NN) { g_offs[i1] = tb + c0; g_cursor[i1] = tb + c0; g_invdeg[i1] = 1.0f / fmaxf((float)c1, 1.0f); }
}
__global__ void fill_kernel(const void* ei) {
    int i = blockIdx.x * blockDim.x + threadIdx.x;
    if (i < NE) {
        int s = edge_at(ei, i);
        int d = edge_at(ei, NE + i);
        s = min(max(s, 0), NN - 1);
        d = min(max(d, 0), NN - 1);
        int p = atomicAdd(&g_cursor[d], 1);
        g_srcs[p] = s;
    }
}

// ---------------- layer-0 GEMM (A frags from global; dual output) ----------------
__global__ __launch_bounds__(512, 1) void sgemm0_kernel(const float* __restrict__ bias, int M)
{
    const int NT = 4;                    // NOUT=128
    int tid = threadIdx.x, wid = tid >> 5, lane = tid & 31;
    int row0 = blockIdx.x * 128;
    int wm = wid & 3, wn = wid >> 2;
    int mrow = wm * 32;
    int ncol = wn * 32;
    int rbB = blockIdx.x * 8 + wm * 2;
    int n16_0 = ncol >> 4;

    float acc[2][2][NT][4];
#pragma unroll
    for (int mx = 0; mx < 2; mx++)
#pragma unroll
        for (int mt = 0; mt < 2; mt++)
#pragma unroll
            for (int nt = 0; nt < NT; nt++)
#pragma unroll
                for (int q = 0; q < 4; q++) acc[mx][mt][nt][q] = 0.f;

#pragma unroll
    for (int ks = 0; ks < 8; ks++) {
        uint4 ah0 = g_afh[(size_t)((rbB + 0) * 8 + ks) * 32 + lane];
        uint4 ah1 = g_afh[(size_t)((rbB + 1) * 8 + ks) * 32 + lane];
        uint4 al0 = g_afl[(size_t)((rbB + 0) * 8 + ks) * 32 + lane];
        uint4 al1 = g_afl[(size_t)((rbB + 1) * 8 + ks) * 32 + lane];
        const uint32_t* ah[2] = { (const uint32_t*)&ah0, (const uint32_t*)&ah1 };
        const uint32_t* al[2] = { (const uint32_t*)&al0, (const uint32_t*)&al1 };
#pragma unroll
        for (int p = 0; p < NT / 2; p++) {
            size_t bidx = (size_t)((n16_0 + p) * 8 + ks) * 32 + lane;
#pragma unroll
            for (int mx = 0; mx < 2; mx++) {
                int loff = mx ? WF_N0 : WF_S0;
                uint4 BH = g_wfh[loff + bidx];
                uint4 BL = g_wfl[loff + bidx];
                const uint32_t* bh = (const uint32_t*)&BH;
                const uint32_t* bl = (const uint32_t*)&BL;
#pragma unroll
                for (int mt = 0; mt < 2; mt++)
#pragma unroll
                    for (int h = 0; h < 2; h++) {
                        float* a = acc[mx][mt][2 * p + h];
                        mma_bf16(a, ah[mt], &bh[h * 2]);
                        mma_bf16(a, ah[mt], &bl[h * 2]);
                        mma_bf16(a, al[mt], &bh[h * 2]);
                    }
            }
        }
    }

#pragma unroll
    for (int mt = 0; mt < 2; mt++) {
        int r0g = row0 + mrow + mt * 16 + (lane >> 2);
        int r1g = r0g + 8;
#pragma unroll
        for (int nt = 0; nt < NT; nt++) {
            int cc = ncol + nt * 8 + (lane & 3) * 2;
            float bx = bias[cc], by = bias[cc + 1];
            if (r0g < M) {
                float2 v;
                v.x = acc[0][mt][nt][0] + bx; v.y = acc[0][mt][nt][1] + by;
                *(float2*)(g_h0 + (size_t)r0g * 128 + cc) = v;
                v.x = acc[1][mt][nt][0]; v.y = acc[1][mt][nt][1];
                *(float2*)(g_y + (size_t)r0g * 128 + cc) = v;
            }
            if (r1g < M) {
                float2 v;
                v.x = acc[0][mt][nt][2] + bx; v.y = acc[0][mt][nt][3] + by;
                *(float2*)(g_h0 + (size_t)r1g * 128 + cc) = v;
                v.x = acc[1][mt][nt][2]; v.y = acc[1][mt][nt][3];
                *(float2*)(g_y + (size_t)r1g * 128 + cc) = v;
            }
        }
    }
}

// ---------------- FUSED: aggregate(prev layer) + frag conversion (smem) + GEMM ----------------
// SELFSEL: 1=g_h0, 2=g_h1   CSEL: 2=g_h1, 0=ext   YIN/YOUT: 0=g_y, 1=g_y2
template <int NOUT, int LOFF_S, int LOFF_N, int SELFSEL, int CSEL, int YINSEL, int YOUTSEL>
__global__ __launch_bounds__(512, 1) void fused_agg_gemm_kernel(
    const float* __restrict__ bias, float* __restrict__ Cext, int M)
{
    extern __shared__ char smem[];
    float (*sh32)[132] = (float(*)[132])(smem + SH32_OFF);

    const float4* yv = (const float4*)(YINSEL ? g_y2 : g_y);
    const float*  self = (SELFSEL == 1) ? g_h0 : g_h1;
    float* CS  = (CSEL == 2) ? g_h1 : Cext;
    float* YO  = YOUTSEL ? g_y2 : g_y;

    int tid = threadIdx.x, wid = tid >> 5, lane = tid & 31;
    int row0 = blockIdx.x * 128;

    // ---- phase 1: aggregate 8 nodes per warp, stage f32 in smem ----
#pragma unroll
    for (int j = 0; j < 8; j++) {
        int r = wid * 8 + j;
        int node = row0 + r;
        float4 o = make_float4(0.f, 0.f, 0.f, 0.f);
        if (node < NN) {
            int s = g_offs[node], e = g_offs[node + 1];
            float4 acc = make_float4(0.f, 0.f, 0.f, 0.f);
            int i = s;
            for (; i + 3 < e; i += 4) {
                int s0 = g_srcs[i], s1 = g_srcs[i + 1], s2 = g_srcs[i + 2], s3 = g_srcs[i + 3];
                float4 v0 = yv[(size_t)s0 * 32 + lane];
                float4 v1 = yv[(size_t)s1 * 32 + lane];
                float4 v2 = yv[(size_t)s2 * 32 + lane];
                float4 v3 = yv[(size_t)s3 * 32 + lane];
                acc.x += (v0.x + v1.x) + (v2.x + v3.x);
                acc.y += (v0.y + v1.y) + (v2.y + v3.y);
                acc.z += (v0.z + v1.z) + (v2.z + v3.z);
                acc.w += (v0.w + v1.w) + (v2.w + v3.w);
            }
            for (; i < e; i++) {
                int s0 = g_srcs[i];
                float4 v0 = yv[(size_t)s0 * 32 + lane];
                acc.x += v0.x; acc.y += v0.y; acc.z += v0.z; acc.w += v0.w;
            }
            float wg = g_invdeg[node];
            float4 sf = ((const float4*)self)[(size_t)node * 32 + lane];
            o.x = fmaxf(sf.x + wg * acc.x, 0.f);
            o.y = fmaxf(sf.y + wg * acc.y, 0.f);
            o.z = fmaxf(sf.z + wg * acc.z, 0.f);
            o.w = fmaxf(sf.w + wg * acc.w, 0.f);
        }
        *(float4*)&sh32[r][lane * 4] = o;
    }
    __syncthreads();

    // ---- phase 2: convert staged f32 -> A fragments in smem (proven pattern) ----
    {
        int tid256 = tid & 255;
        int ks = tid256 >> 5, lf = tid256 & 31;
        int r0b = lf >> 2, r1b = r0b + 8;
        int cp0 = ks * 8 + (lf & 3), cp1 = cp0 + 4;
#pragma unroll
        for (int it = 0; it < 4; it++) {
            int rbl = it * 2 + (tid >> 8);
            int r0 = rbl * 16 + r0b, r1 = rbl * 16 + r1b;
            uint4 h, l;
            pack2(sh32[r0][cp0 * 2], sh32[r0][cp0 * 2 + 1], h.x, l.x);
            pack2(sh32[r1][cp0 * 2], sh32[r1][cp0 * 2 + 1], h.y, l.y);
            pack2(sh32[r0][cp1 * 2], sh32[r0][cp1 * 2 + 1], h.z, l.z);
            pack2(sh32[r1][cp1 * 2], sh32[r1][cp1 * 2 + 1], h.w, l.w);
            int idx = (rbl * 8 + ks) * 32 + lf;
            *(uint4*)(smem + AFH_OFF + idx * 16) = h;
            *(uint4*)(smem + AFL_OFF + idx * 16) = l;
        }
    }
    __syncthreads();

    // ---- phase 3: dual-output GEMM, A from smem ----
    const int NT = NOUT / 32;
    int wm = wid & 3, wn = wid >> 2;
    int mrow = wm * 32;
    int ncol = wn * (NT * 8);
    int n16_0 = ncol >> 4;

    float acc[2][2][NT][4];
#pragma unroll
    for (int mx = 0; mx < 2; mx++)
#pragma unroll
        for (int mt = 0; mt < 2; mt++)
#pragma unroll
            for (int nt = 0; nt < NT; nt++)
#pragma unroll
                for (int q = 0; q < 4; q++) acc[mx][mt][nt][q] = 0.f;

#pragma unroll
    for (int ks = 0; ks < 8; ks++) {
        int ia0 = ((wm * 2 + 0) * 8 + ks) * 32 + lane;
        int ia1 = ((wm * 2 + 1) * 8 + ks) * 32 + lane;
        uint4 ah0 = *(const uint4*)(smem + AFH_OFF + ia0 * 16);
        uint4 ah1 = *(const uint4*)(smem + AFH_OFF + ia1 * 16);
        uint4 al0 = *(const uint4*)(smem + AFL_OFF + ia0 * 16);
        uint4 al1 = *(const uint4*)(smem + AFL_OFF + ia1 * 16);
        const uint32_t* ah[2] = { (const uint32_t*)&ah0, (const uint32_t*)&ah1 };
        const uint32_t* al[2] = { (const uint32_t*)&al0, (const uint32_t*)&al1 };
#pragma unroll
        for (int p = 0; p < NT / 2; p++) {
            size_t bidx = (size_t)((n16_0 + p) * 8 + ks) * 32 + lane;
#pragma unroll
            for (int mx = 0; mx < 2; mx++) {
                int loff = mx ? LOFF_N : LOFF_S;
                uint4 BH = g_wfh[loff + bidx];
                uint4 BL = g_wfl[loff + bidx];
                const uint32_t* bh = (const uint32_t*)&BH;
                const uint32_t* bl = (const uint32_t*)&BL;
#pragma unroll
                for (int mt = 0; mt < 2; mt++)
#pragma unroll
                    for (int h = 0; h < 2; h++) {
                        float* a = acc[mx][mt][2 * p + h];
                        mma_bf16(a, ah[mt], &bh[h * 2]);
                        mma_bf16(a, ah[mt], &bl[h * 2]);
                        mma_bf16(a, al[mt], &bh[h * 2]);
                    }
            }
        }
    }

#pragma unroll
    for (int mt = 0; mt < 2; mt++) {
        int r0g = row0 + mrow + mt * 16 + (lane >> 2);
        int r1g = r0g + 8;
#pragma unroll
        for (int nt = 0; nt < NT; nt++) {
            int cc = ncol + nt * 8 + (lane & 3) * 2;
            float bx = bias ? bias[cc] : 0.f;
            float by = bias ? bias[cc + 1] : 0.f;
            if (r0g < M) {
                float2 v;
                v.x = acc[0][mt][nt][0] + bx; v.y = acc[0][mt][nt][1] + by;
                *(float2*)(CS + (size_t)r0g * NOUT + cc) = v;
                v.x = acc[1][mt][nt][0]; v.y = acc[1][mt][nt][1];
                *(float2*)(YO + (size_t)r0g * NOUT + cc) = v;
            }
            if (r1g < M) {
                float2 v;
                v.x = acc[0][mt][nt][2] + bx; v.y = acc[0][mt][nt][3] + by;
                *(float2*)(CS + (size_t)r1g * NOUT + cc) = v;
                v.x = acc[1][mt][nt][2]; v.y = acc[1][mt][nt][3];
                *(float2*)(YO + (size_t)r1g * NOUT + cc) = v;
            }
        }
    }
}

// ---------------- final aggregate (D=64, reads g_y, writes d_out, no relu) ----------------
__global__ void agg_final_kernel(float* __restrict__ out)
{
    const float4* yv = (const float4*)g_y;
    const int CH = 16;
    int gt   = blockIdx.x * blockDim.x + threadIdx.x;
    int warp = gt >> 5;
    int lane = gt & 31;
    int node = warp * 2 + lane / CH;
    int c    = lane % CH;
    if (node >= NN) return;

    int s = g_offs[node], e = g_offs[node + 1];
    float4 acc = make_float4(0.f, 0.f, 0.f, 0.f);
    int i = s;
    for (; i + 3 < e; i += 4) {
        int s0 = g_srcs[i], s1 = g_srcs[i + 1], s2 = g_srcs[i + 2], s3 = g_srcs[i + 3];
        float4 v0 = yv[(size_t)s0 * CH + c];
        float4 v1 = yv[(size_t)s1 * CH + c];
        float4 v2 = yv[(size_t)s2 * CH + c];
        float4 v3 = yv[(size_t)s3 * CH + c];
        acc.x += (v0.x + v1.x) + (v2.x + v3.x);
        acc.y += (v0.y + v1.y) + (v2.y + v3.y);
        acc.z += (v0.z + v1.z) + (v2.z + v3.z);
        acc.w += (v0.w + v1.w) + (v2.w + v3.w);
    }
    for (; i < e; i++) {
        int s0 = g_srcs[i];
        float4 v0 = yv[(size_t)s0 * CH + c];
        acc.x += v0.x; acc.y += v0.y; acc.z += v0.z; acc.w += v0.w;
    }
    float w = g_invdeg[node];
    float4* op = (float4*)out + (size_t)node * CH + c;
    float4 o = *op;
    o.x += w * acc.x; o.y += w * acc.y; o.z += w * acc.z; o.w += w * acc.w;
    *op = o;
}

// ---------------- launch ----------------
extern "C" void kernel_launch(void* const* d_in, const int* in_sizes, int n_in,
                              void* d_out, int out_size)
{
    const float* x   = (const float*)d_in[0];
    const void*  ei  = d_in[1];
    const float* Ws0 = (const float*)d_in[2];
    const float* Wn0 = (const float*)d_in[3];
    const float* b0  = (const float*)d_in[4];
    const float* Ws1 = (const float*)d_in[5];
    const float* Wn1 = (const float*)d_in[6];
    const float* b1  = (const float*)d_in[7];
    const float* Ws2 = (const float*)d_in[8];
    const float* Wn2 = (const float*)d_in[9];
    const float* b2  = (const float*)d_in[10];
    float* out = (float*)d_out;

    cudaFuncSetAttribute(fused_agg_gemm_kernel<128, WF_S1, WF_N1, 1, 2, 0, 1>,
                         cudaFuncAttributeMaxDynamicSharedMemorySize, FUSED_SMEM);
    cudaFuncSetAttribute(fused_agg_gemm_kernel<64, WF_S2, WF_N2, 2, 0, 1, 0>,
                         cudaFuncAttributeMaxDynamicSharedMemorySize, FUSED_SMEM);

    const int tb = 256;

    // fork-join: CSR build overlaps conv+GEMM0 on a side stream
    cudaStream_t s2;
    cudaStreamCreateWithFlags(&s2, cudaStreamNonBlocking);
    cudaEvent_t evF, evJ;
    cudaEventCreateWithFlags(&evF, cudaEventDisableTiming);
    cudaEventCreateWithFlags(&evJ, cudaEventDisableTiming);

    init_flag_kernel<<<1, 1>>>();
    detect_kernel<<<(2 * NE + tb - 1) / tb, tb>>>(ei);
    cudaEventRecord(evF, 0);
    cudaStreamWaitEvent(s2, evF, 0);

    // side stream: CSR build
    zero_count_kernel<<<(NN + tb - 1) / tb, tb, 0, s2>>>();
    hist_kernel<<<(NE + tb - 1) / tb, tb, 0, s2>>>(ei);
    scan1_kernel<<<SCAN_NB, SCAN_THR, 0, s2>>>();
    scan2_kernel<<<1, 128, 0, s2>>>();
    scan3_kernel<<<SCAN_NB, SCAN_THR, 0, s2>>>();
    fill_kernel<<<(NE + tb - 1) / tb, tb, 0, s2>>>(ei);
    cudaEventRecord(evJ, s2);

    // main stream
    conv_all_kernel<<<NRB + 40, 256>>>(x, Ws0, Wn0, Ws1, Wn1, Ws2, Wn2);
    sgemm0_kernel<<<391, 512>>>(b0, NN);
    cudaStreamWaitEvent(0, evJ, 0);

    // fused layer 1: agg(h0, yA) -> GEMM1 -> (g_h1, yB)
    fused_agg_gemm_kernel<128, WF_S1, WF_N1, 1, 2, 0, 1>
        <<<391, 512, FUSED_SMEM>>>(b1, nullptr, NN);
    // fused layer 2: agg(h1, yB) -> GEMM2 -> (out + b2, yA)
    fused_agg_gemm_kernel<64, WF_S2, WF_N2, 2, 0, 1, 0>
        <<<391, 512, FUSED_SMEM>>>(b2, out, NN);
    agg_final_kernel<<<(NN * 16 + 255) / 256, 256>>>(out);
}